// round 2
// baseline (speedup 1.0000x reference)
#include <cuda_runtime.h>

#define NEG_SLOPE 0.2f

static const int NMAX = 50000;
static const int EMAX = 800000;

// ---------------- scratch (static device globals; no allocation allowed) ----
__device__ __align__(16) float g_h1[NMAX * 128];     // layer1 node features (post-GEMM)
__device__ __align__(16) float g_out1[NMAX * 128];   // layer1 output = layer2 input
__device__ __align__(16) float g_h2[NMAX * 40];      // layer2 node features (post-GEMM)
__device__ __align__(16) float g_asrc1[NMAX * 8];
__device__ __align__(16) float g_adst1[NMAX * 8];
__device__ __align__(16) float g_asrc2[NMAX];
__device__ __align__(16) float g_adst2[NMAX];
__device__ int   g_cnt[NMAX];
__device__ int   g_off[NMAX + 1];
__device__ int   g_cursor[NMAX];
__device__ int   g_csr[EMAX];          // src node ids grouped by dst

__device__ __forceinline__ float lrelu(float v) { return v > 0.f ? v : NEG_SLOPE * v; }

// ---------------- CSR build -------------------------------------------------
__global__ void zero_cnt_kernel(int n) {
    int i = blockIdx.x * blockDim.x + threadIdx.x;
    if (i < n) g_cnt[i] = 0;
}

__global__ void hist_kernel(const int* __restrict__ dst, int E) {
    int e = blockIdx.x * blockDim.x + threadIdx.x;
    if (e < E) atomicAdd(&g_cnt[dst[e]], 1);
}

// single-block exclusive scan over g_cnt -> g_off (n up to NMAX), g_off[n]=total
__global__ void scan_kernel(int n) {
    __shared__ int sh[1024];
    __shared__ int carry_s;
    int tid = threadIdx.x;
    if (tid == 0) carry_s = 0;
    __syncthreads();
    for (int base = 0; base < n; base += 1024) {
        int v = (base + tid < n) ? g_cnt[base + tid] : 0;
        sh[tid] = v;
        __syncthreads();
        for (int s = 1; s < 1024; s <<= 1) {
            int t = (tid >= s) ? sh[tid - s] : 0;
            __syncthreads();
            sh[tid] += t;
            __syncthreads();
        }
        int incl = sh[tid];
        int carry = carry_s;
        if (base + tid < n) g_off[base + tid] = carry + incl - v;
        __syncthreads();
        if (tid == 1023) carry_s = carry + incl;
        __syncthreads();
    }
    if (tid == 0) g_off[n] = carry_s;
}

__global__ void init_cursor_kernel(int n) {
    int i = blockIdx.x * blockDim.x + threadIdx.x;
    if (i < n) g_cursor[i] = g_off[i];
}

__global__ void scatter_kernel(const int* __restrict__ src,
                               const int* __restrict__ dst, int E) {
    int e = blockIdx.x * blockDim.x + threadIdx.x;
    if (e < E) {
        int d = dst[e];
        int pos = atomicAdd(&g_cursor[d], 1);
        g_csr[pos] = src[e];
    }
}

// ---------------- GEMM: Y[N,COLS] = X[N,128] @ W[128,COLS] -----------------
// block: (COLS/4)*8 threads, 32 rows per block; W fully resident in smem.
template <int COLS>
__global__ void gemm_kernel(const float* __restrict__ X, const float* __restrict__ W,
                            float* __restrict__ Y, int N) {
    extern __shared__ float sm[];
    float* ws = sm;                  // 128*COLS floats
    float* xs = sm + 128 * COLS;     // 32*132 floats (padded stride)
    const int CG = COLS / 4;
    int tid = threadIdx.x;
    int nthreads = blockDim.x;

    for (int i = tid; i < 32 * COLS; i += nthreads)   // 128*COLS/4 float4s
        ((float4*)ws)[i] = ((const float4*)W)[i];

    int row0 = blockIdx.x * 32;
    for (int i = tid; i < 32 * 32; i += nthreads) {   // 32 rows x 32 float4s
        int r = i >> 5, k4 = i & 31;
        int row = row0 + r;
        float4 v = make_float4(0.f, 0.f, 0.f, 0.f);
        if (row < N) v = *(const float4*)&X[row * 128 + k4 * 4];
        *(float4*)&xs[r * 132 + k4 * 4] = v;
    }
    __syncthreads();

    int cg = tid % CG;
    int rg = tid / CG;
    float acc[4][4];
#pragma unroll
    for (int r = 0; r < 4; r++)
#pragma unroll
        for (int c = 0; c < 4; c++) acc[r][c] = 0.f;

#pragma unroll 4
    for (int k = 0; k < 128; k++) {
        float4 w4 = *(float4*)&ws[k * COLS + cg * 4];
#pragma unroll
        for (int r = 0; r < 4; r++) {
            float xv = xs[(rg * 4 + r) * 132 + k];
            acc[r][0] = fmaf(xv, w4.x, acc[r][0]);
            acc[r][1] = fmaf(xv, w4.y, acc[r][1]);
            acc[r][2] = fmaf(xv, w4.z, acc[r][2]);
            acc[r][3] = fmaf(xv, w4.w, acc[r][3]);
        }
    }
#pragma unroll
    for (int r = 0; r < 4; r++) {
        int row = row0 + rg * 4 + r;
        if (row < N)
            *(float4*)&Y[row * COLS + cg * 4] =
                make_float4(acc[r][0], acc[r][1], acc[r][2], acc[r][3]);
    }
}

// ---------------- attention logits ------------------------------------------
// layer1: warp per node; lane -> (head=lane/4, quad=lane%4) of the 128-wide row
__global__ void att1_kernel(const float* __restrict__ att_src,
                            const float* __restrict__ att_dst, int N) {
    int node = (blockIdx.x * blockDim.x + threadIdx.x) >> 5;
    if (node >= N) return;
    int lane = threadIdx.x & 31;
    int h = lane >> 2, q = lane & 3;
    float4 hv = *(const float4*)&g_h1[node * 128 + lane * 4];
    float4 as = *(const float4*)&att_src[lane * 4];
    float4 ad = *(const float4*)&att_dst[lane * 4];
    float s1 = hv.x * as.x + hv.y * as.y + hv.z * as.z + hv.w * as.w;
    float s2 = hv.x * ad.x + hv.y * ad.y + hv.z * ad.z + hv.w * ad.w;
    s1 += __shfl_xor_sync(0xffffffffu, s1, 1);
    s1 += __shfl_xor_sync(0xffffffffu, s1, 2);
    s2 += __shfl_xor_sync(0xffffffffu, s2, 1);
    s2 += __shfl_xor_sync(0xffffffffu, s2, 2);
    if (q == 0) {
        g_asrc1[node * 8 + h] = s1;
        g_adst1[node * 8 + h] = s2;
    }
}

__global__ void att2_kernel(const float* __restrict__ att_src,
                            const float* __restrict__ att_dst, int N) {
    int node = (blockIdx.x * blockDim.x + threadIdx.x) >> 5;
    if (node >= N) return;
    int lane = threadIdx.x & 31;
    float s1 = 0.f, s2 = 0.f;
    for (int c = lane; c < 40; c += 32) {
        float v = g_h2[node * 40 + c];
        s1 = fmaf(v, att_src[c], s1);
        s2 = fmaf(v, att_dst[c], s2);
    }
#pragma unroll
    for (int o = 16; o; o >>= 1) {
        s1 += __shfl_xor_sync(0xffffffffu, s1, o);
        s2 += __shfl_xor_sync(0xffffffffu, s2, o);
    }
    if (lane == 0) {
        g_asrc2[node] = s1;
        g_adst2[node] = s2;
    }
}

// ---------------- aggregation (warp per destination node) -------------------
// layer1: H=8,C=16. lane -> head lane/4, channels lane*4..lane*4+3 (float4).
// Two passes over in-edges: max, then exp+accumulate. Self-loop analytic.
__global__ void agg1_kernel(const float* __restrict__ bias, int N) {
    int node = (blockIdx.x * blockDim.x + threadIdx.x) >> 5;
    if (node >= N) return;
    int lane = threadIdx.x & 31;
    int h = lane >> 2;
    int beg = g_off[node], end = g_off[node + 1];

    float adst = g_adst1[node * 8 + h];
    float aself = lrelu(g_asrc1[node * 8 + h] + adst);
    float m = aself;
    for (int e = beg; e < end; e++) {
        int s = g_csr[e];
        m = fmaxf(m, lrelu(g_asrc1[s * 8 + h] + adst));
    }
    float w = __expf(aself - m);
    float denom = w;
    float4 hv = *(const float4*)&g_h1[node * 128 + lane * 4];
    float4 acc = make_float4(w * hv.x, w * hv.y, w * hv.z, w * hv.w);
    for (int e = beg; e < end; e++) {
        int s = g_csr[e];
        float wv = __expf(lrelu(g_asrc1[s * 8 + h] + adst) - m);
        denom += wv;
        float4 v = *(const float4*)&g_h1[s * 128 + lane * 4];
        acc.x = fmaf(wv, v.x, acc.x);
        acc.y = fmaf(wv, v.y, acc.y);
        acc.z = fmaf(wv, v.z, acc.z);
        acc.w = fmaf(wv, v.w, acc.w);
    }
    float inv = 1.f / (denom + 1e-16f);
    float4 b = *(const float4*)&bias[lane * 4];
    *(float4*)&g_out1[node * 128 + lane * 4] =
        make_float4(fmaf(acc.x, inv, b.x), fmaf(acc.y, inv, b.y),
                    fmaf(acc.z, inv, b.z), fmaf(acc.w, inv, b.w));
}

// layer2: H=1, C=40. lanes 0..9 carry float4 channels; all lanes track softmax.
__global__ void agg2_kernel(const float* __restrict__ bias, float* __restrict__ out, int N) {
    int node = (blockIdx.x * blockDim.x + threadIdx.x) >> 5;
    if (node >= N) return;
    int lane = threadIdx.x & 31;
    int beg = g_off[node], end = g_off[node + 1];

    float adst = g_adst2[node];
    float aself = lrelu(g_asrc2[node] + adst);
    float m = aself;
    for (int e = beg; e < end; e++) {
        int s = g_csr[e];
        m = fmaxf(m, lrelu(g_asrc2[s] + adst));
    }
    float w = __expf(aself - m);
    float denom = w;
    float4 acc = make_float4(0.f, 0.f, 0.f, 0.f);
    if (lane < 10) {
        float4 hv = *(const float4*)&g_h2[node * 40 + lane * 4];
        acc = make_float4(w * hv.x, w * hv.y, w * hv.z, w * hv.w);
    }
    for (int e = beg; e < end; e++) {
        int s = g_csr[e];
        float wv = __expf(lrelu(g_asrc2[s] + adst) - m);
        denom += wv;
        if (lane < 10) {
            float4 v = *(const float4*)&g_h2[s * 40 + lane * 4];
            acc.x = fmaf(wv, v.x, acc.x);
            acc.y = fmaf(wv, v.y, acc.y);
            acc.z = fmaf(wv, v.z, acc.z);
            acc.w = fmaf(wv, v.w, acc.w);
        }
    }
    float inv = 1.f / (denom + 1e-16f);
    if (lane < 10) {
        float4 b = *(const float4*)&bias[lane * 4];
        *(float4*)&out[node * 40 + lane * 4] =
            make_float4(fmaf(acc.x, inv, b.x), fmaf(acc.y, inv, b.y),
                        fmaf(acc.z, inv, b.z), fmaf(acc.w, inv, b.w));
    }
}

// ---------------- launch ----------------------------------------------------
extern "C" void kernel_launch(void* const* d_in, const int* in_sizes, int n_in,
                              void* d_out, int out_size) {
    const float* x        = (const float*)d_in[0];
    const int*   ei       = (const int*)d_in[1];   // JAX default x64 disabled -> int32
    const float* W1       = (const float*)d_in[2];
    const float* att_src1 = (const float*)d_in[3];
    const float* att_dst1 = (const float*)d_in[4];
    const float* bias1    = (const float*)d_in[5];
    const float* W2       = (const float*)d_in[6];
    const float* att_src2 = (const float*)d_in[7];
    const float* att_dst2 = (const float*)d_in[8];
    const float* bias2    = (const float*)d_in[9];
    float* out = (float*)d_out;

    int N = in_sizes[0] / 128;
    int E = in_sizes[1] / 2;
    const int* src = ei;
    const int* dst = ei + E;

    float *h1p, *out1p, *h2p;
    cudaGetSymbolAddress((void**)&h1p, g_h1);
    cudaGetSymbolAddress((void**)&out1p, g_out1);
    cudaGetSymbolAddress((void**)&h2p, g_h2);

    int smem1 = (128 * 128 + 32 * 132) * 4;  // 82432 B
    int smem2 = (128 * 40 + 32 * 132) * 4;   // 37376 B
    cudaFuncSetAttribute(gemm_kernel<128>, cudaFuncAttributeMaxDynamicSharedMemorySize, smem1);

    int eb = (E + 255) / 256;
    int nb = (N + 255) / 256;
    int wb = (N + 7) / 8;              // warp-per-node kernels, 8 warps/block
    int gb = (N + 31) / 32;            // gemm row tiles

    // CSR build (shared by both layers)
    zero_cnt_kernel<<<nb, 256>>>(N);
    hist_kernel<<<eb, 256>>>(dst, E);
    scan_kernel<<<1, 1024>>>(N);
    init_cursor_kernel<<<nb, 256>>>(N);
    scatter_kernel<<<eb, 256>>>(src, dst, E);

    // layer 1
    gemm_kernel<128><<<gb, 32 * 8, smem1>>>(x, W1, h1p, N);
    att1_kernel<<<wb, 256>>>(att_src1, att_dst1, N);
    agg1_kernel<<<wb, 256>>>(bias1, N);

    // layer 2
    gemm_kernel<40><<<gb, 10 * 8, smem2>>>(out1p, W2, h2p, N);
    att2_kernel<<<wb, 256>>>(att_src2, att_dst2, N);
    agg2_kernel<<<wb, 256>>>(bias2, out, N);
}

// round 3
// speedup vs baseline: 1.2121x; 1.2121x over previous
#include <cuda_runtime.h>
#include <cstdint>

#define NEG_SLOPE 0.2f

static const int NMAX = 50000;
static const int EMAX = 800000;

// ---------------- scratch ---------------------------------------------------
__device__ __align__(16) float g_h1[NMAX * 128];
__device__ __align__(16) float g_out1[NMAX * 128];
__device__ __align__(16) float g_h2[NMAX * 40];
__device__ __align__(16) float g_asrc1[NMAX * 8];
__device__ __align__(16) float g_adst1[NMAX * 8];
__device__ __align__(16) float g_asrc2[NMAX];
__device__ __align__(16) float g_adst2[NMAX];
__device__ int   g_cnt[NMAX];
__device__ int   g_off[NMAX + 1];
__device__ int   g_cursor[NMAX];
__device__ int   g_csr[EMAX];

__device__ __forceinline__ float lrelu(float v) { return v > 0.f ? v : NEG_SLOPE * v; }
__device__ __forceinline__ uint32_t f2tf32(float f) {
    uint32_t u;
    asm("cvt.rna.tf32.f32 %0, %1;" : "=r"(u) : "f"(f));
    return u;
}

// ---------------- CSR build -------------------------------------------------
__global__ void hist_kernel(const int* __restrict__ dst, int E) {
    int e = blockIdx.x * blockDim.x + threadIdx.x;
    if (e < E) atomicAdd(&g_cnt[dst[e]], 1);
}

// one-pass scan: 1024 threads, thread-sequential chunks + warp/block scan
__global__ void scan_kernel(int n) {
    __shared__ int wsum[32];
    int tid = threadIdx.x;
    int lane = tid & 31, w = tid >> 5;
    int chunk = (n + 1023) >> 10;
    int beg = tid * chunk;
    int end = min(beg + chunk, n);
    int s = 0;
    for (int i = beg; i < end; i++) s += g_cnt[i];
    int v = s;
#pragma unroll
    for (int o = 1; o < 32; o <<= 1) {
        int t = __shfl_up_sync(0xffffffffu, v, o);
        if (lane >= o) v += t;
    }
    if (lane == 31) wsum[w] = v;
    __syncthreads();
    if (w == 0) {
        int x = wsum[lane];
#pragma unroll
        for (int o = 1; o < 32; o <<= 1) {
            int t = __shfl_up_sync(0xffffffffu, x, o);
            if (lane >= o) x += t;
        }
        wsum[lane] = x;
    }
    __syncthreads();
    int run = v - s + (w ? wsum[w - 1] : 0);   // exclusive prefix of this thread
    for (int i = beg; i < end; i++) {
        int c = g_cnt[i];
        g_off[i] = run;
        run += c;
    }
    if (tid == 1023) g_off[n] = run;
}

__global__ void scatter_kernel(const int* __restrict__ src,
                               const int* __restrict__ dst, int E) {
    int e = blockIdx.x * blockDim.x + threadIdx.x;
    if (e < E) {
        int d = dst[e];
        int pos = atomicAdd(&g_cursor[d], 1);
        g_csr[pos] = src[e];
    }
}

// ---------------- layer1 GEMM: TF32 tensor cores + fused attention logits ---
// Y[N,128] = X[N,128] @ W[128,128]; also writes g_asrc1/g_adst1 per (node,head).
// Block: 256 thr (8 warps), tile 64 rows x 128 cols. warp = 16 rows x 64 cols.
__global__ __launch_bounds__(256) void gemm1_tf32_kernel(
    const float* __restrict__ X, const float* __restrict__ W,
    const float* __restrict__ att_src, const float* __restrict__ att_dst,
    float* __restrict__ Y, int N) {
    const int WS = 136, XS = 132;
    extern __shared__ float smf[];
    uint32_t* ws = (uint32_t*)smf;                 // 128 x WS (tf32 bits)
    uint32_t* xs = (uint32_t*)(smf + 128 * WS);    // 64 x XS  (tf32 bits)
    float* satt = smf + 128 * WS + 64 * XS;        // 256 floats: [src|dst]
    int tid = threadIdx.x;

    // stage W (convert to tf32)
    for (int i = tid; i < 128 * 32; i += 256) {
        int k = i >> 5, n4 = (i & 31) * 4;
        float4 v = *(const float4*)&W[k * 128 + n4];
        uint32_t* p = &ws[k * WS + n4];
        p[0] = f2tf32(v.x); p[1] = f2tf32(v.y); p[2] = f2tf32(v.z); p[3] = f2tf32(v.w);
    }
    satt[tid] = (tid < 128) ? att_src[tid] : att_dst[tid - 128];

    // stage X tile (convert to tf32)
    int row0 = blockIdx.x * 64;
    for (int i = tid; i < 64 * 32; i += 256) {
        int r = i >> 5, k4 = (i & 31) * 4;
        int row = row0 + r;
        float4 v = (row < N) ? *(const float4*)&X[row * 128 + k4]
                             : make_float4(0.f, 0.f, 0.f, 0.f);
        uint32_t* p = &xs[r * XS + k4];
        p[0] = f2tf32(v.x); p[1] = f2tf32(v.y); p[2] = f2tf32(v.z); p[3] = f2tf32(v.w);
    }
    __syncthreads();

    int lane = tid & 31, wid = tid >> 5;
    int wm = (wid >> 1) * 16;          // warp row offset within tile
    int wn = (wid & 1) * 64;           // warp col offset
    int q = lane & 3, g = lane >> 2;

    float c[8][4];
#pragma unroll
    for (int nt = 0; nt < 8; nt++)
#pragma unroll
        for (int j = 0; j < 4; j++) c[nt][j] = 0.f;

#pragma unroll
    for (int kt = 0; kt < 16; kt++) {
        int k0 = kt * 8;
        int ar = wm + g;
        uint32_t a0 = xs[ar * XS + k0 + q];
        uint32_t a1 = xs[(ar + 8) * XS + k0 + q];
        uint32_t a2 = xs[ar * XS + k0 + q + 4];
        uint32_t a3 = xs[(ar + 8) * XS + k0 + q + 4];
#pragma unroll
        for (int nt = 0; nt < 8; nt++) {
            int bn = wn + nt * 8 + g;
            uint32_t b0 = ws[(k0 + q) * WS + bn];
            uint32_t b1 = ws[(k0 + q + 4) * WS + bn];
            asm volatile(
                "mma.sync.aligned.m16n8k8.row.col.f32.tf32.tf32.f32 "
                "{%0,%1,%2,%3},{%4,%5,%6,%7},{%8,%9},{%0,%1,%2,%3};"
                : "+f"(c[nt][0]), "+f"(c[nt][1]), "+f"(c[nt][2]), "+f"(c[nt][3])
                : "r"(a0), "r"(a1), "r"(a2), "r"(a3), "r"(b0), "r"(b1));
        }
    }

    // epilogue: store Y + fused per-head attention logits
    int r_lo = row0 + wm + g;
    int r_hi = r_lo + 8;
    float ps_lo[4] = {0, 0, 0, 0}, pd_lo[4] = {0, 0, 0, 0};
    float ps_hi[4] = {0, 0, 0, 0}, pd_hi[4] = {0, 0, 0, 0};
#pragma unroll
    for (int nt = 0; nt < 8; nt++) {
        int col = wn + nt * 8 + 2 * q;
        float as0 = satt[col], as1 = satt[col + 1];
        float ad0 = satt[128 + col], ad1 = satt[128 + col + 1];
        int lh = nt >> 1;
        ps_lo[lh] += c[nt][0] * as0 + c[nt][1] * as1;
        pd_lo[lh] += c[nt][0] * ad0 + c[nt][1] * ad1;
        ps_hi[lh] += c[nt][2] * as0 + c[nt][3] * as1;
        pd_hi[lh] += c[nt][2] * ad0 + c[nt][3] * ad1;
        if (r_lo < N) *(float2*)&Y[r_lo * 128 + col] = make_float2(c[nt][0], c[nt][1]);
        if (r_hi < N) *(float2*)&Y[r_hi * 128 + col] = make_float2(c[nt][2], c[nt][3]);
    }
#pragma unroll
    for (int lh = 0; lh < 4; lh++) {
#pragma unroll
        for (int o = 1; o <= 2; o <<= 1) {
            ps_lo[lh] += __shfl_xor_sync(0xffffffffu, ps_lo[lh], o);
            pd_lo[lh] += __shfl_xor_sync(0xffffffffu, pd_lo[lh], o);
            ps_hi[lh] += __shfl_xor_sync(0xffffffffu, ps_hi[lh], o);
            pd_hi[lh] += __shfl_xor_sync(0xffffffffu, pd_hi[lh], o);
        }
    }
    if (q == 0) {
        int hb = wn >> 4;
#pragma unroll
        for (int lh = 0; lh < 4; lh++) {
            int h = hb + lh;
            if (r_lo < N) { g_asrc1[r_lo * 8 + h] = ps_lo[lh]; g_adst1[r_lo * 8 + h] = pd_lo[lh]; }
            if (r_hi < N) { g_asrc1[r_hi * 8 + h] = ps_hi[lh]; g_adst1[r_hi * 8 + h] = pd_hi[lh]; }
        }
    }
}

// ---------------- layer2 GEMM (fp32, COLS=40) -------------------------------
template <int COLS>
__global__ void gemm_kernel(const float* __restrict__ X, const float* __restrict__ W,
                            float* __restrict__ Y, int N) {
    extern __shared__ float sm[];
    float* wsm = sm;                 // 128*COLS
    float* xsm = sm + 128 * COLS;    // 32*132
    const int CG = COLS / 4;
    int tid = threadIdx.x;
    int nthreads = blockDim.x;

    for (int i = tid; i < 32 * COLS; i += nthreads)
        ((float4*)wsm)[i] = ((const float4*)W)[i];

    int row0 = blockIdx.x * 32;
    for (int i = tid; i < 32 * 32; i += nthreads) {
        int r = i >> 5, k4 = i & 31;
        int row = row0 + r;
        float4 v = make_float4(0.f, 0.f, 0.f, 0.f);
        if (row < N) v = *(const float4*)&X[row * 128 + k4 * 4];
        *(float4*)&xsm[r * 132 + k4 * 4] = v;
    }
    __syncthreads();

    int cg = tid % CG;
    int rg = tid / CG;
    float acc[4][4];
#pragma unroll
    for (int r = 0; r < 4; r++)
#pragma unroll
        for (int cc = 0; cc < 4; cc++) acc[r][cc] = 0.f;

#pragma unroll 4
    for (int k = 0; k < 128; k++) {
        float4 w4 = *(float4*)&wsm[k * COLS + cg * 4];
#pragma unroll
        for (int r = 0; r < 4; r++) {
            float xv = xsm[(rg * 4 + r) * 132 + k];
            acc[r][0] = fmaf(xv, w4.x, acc[r][0]);
            acc[r][1] = fmaf(xv, w4.y, acc[r][1]);
            acc[r][2] = fmaf(xv, w4.z, acc[r][2]);
            acc[r][3] = fmaf(xv, w4.w, acc[r][3]);
        }
    }
#pragma unroll
    for (int r = 0; r < 4; r++) {
        int row = row0 + rg * 4 + r;
        if (row < N)
            *(float4*)&Y[row * COLS + cg * 4] =
                make_float4(acc[r][0], acc[r][1], acc[r][2], acc[r][3]);
    }
}

// ---------------- layer2 attention logits -----------------------------------
__global__ void att2_kernel(const float* __restrict__ att_src,
                            const float* __restrict__ att_dst, int N) {
    int node = (blockIdx.x * blockDim.x + threadIdx.x) >> 5;
    if (node >= N) return;
    int lane = threadIdx.x & 31;
    float s1 = 0.f, s2 = 0.f;
    for (int cc = lane; cc < 40; cc += 32) {
        float v = g_h2[node * 40 + cc];
        s1 = fmaf(v, att_src[cc], s1);
        s2 = fmaf(v, att_dst[cc], s2);
    }
#pragma unroll
    for (int o = 16; o; o >>= 1) {
        s1 += __shfl_xor_sync(0xffffffffu, s1, o);
        s2 += __shfl_xor_sync(0xffffffffu, s2, o);
    }
    if (lane == 0) {
        g_asrc2[node] = s1;
        g_adst2[node] = s2;
    }
}

// ---------------- aggregation (warp per destination node) -------------------
__global__ void agg1_kernel(const float* __restrict__ bias, int N) {
    int node = (blockIdx.x * blockDim.x + threadIdx.x) >> 5;
    if (node >= N) return;
    int lane = threadIdx.x & 31;
    int h = lane >> 2;
    int beg = g_off[node], end = g_off[node + 1];

    float adst = g_adst1[node * 8 + h];
    float aself = lrelu(g_asrc1[node * 8 + h] + adst);
    float m = aself;
    for (int e = beg; e < end; e++) {
        int s = g_csr[e];
        m = fmaxf(m, lrelu(g_asrc1[s * 8 + h] + adst));
    }
    float w = __expf(aself - m);
    float denom = w;
    float4 hv = *(const float4*)&g_h1[node * 128 + lane * 4];
    float4 acc = make_float4(w * hv.x, w * hv.y, w * hv.z, w * hv.w);
    for (int e = beg; e < end; e++) {
        int s = g_csr[e];
        float wv = __expf(lrelu(g_asrc1[s * 8 + h] + adst) - m);
        denom += wv;
        float4 v = *(const float4*)&g_h1[s * 128 + lane * 4];
        acc.x = fmaf(wv, v.x, acc.x);
        acc.y = fmaf(wv, v.y, acc.y);
        acc.z = fmaf(wv, v.z, acc.z);
        acc.w = fmaf(wv, v.w, acc.w);
    }
    float inv = 1.f / (denom + 1e-16f);
    float4 b = *(const float4*)&bias[lane * 4];
    *(float4*)&g_out1[node * 128 + lane * 4] =
        make_float4(fmaf(acc.x, inv, b.x), fmaf(acc.y, inv, b.y),
                    fmaf(acc.z, inv, b.z), fmaf(acc.w, inv, b.w));
}

__global__ void agg2_kernel(const float* __restrict__ bias, float* __restrict__ out, int N) {
    int node = (blockIdx.x * blockDim.x + threadIdx.x) >> 5;
    if (node >= N) return;
    int lane = threadIdx.x & 31;
    int beg = g_off[node], end = g_off[node + 1];

    float adst = g_adst2[node];
    float aself = lrelu(g_asrc2[node] + adst);
    float m = aself;
    for (int e = beg; e < end; e++) {
        int s = g_csr[e];
        m = fmaxf(m, lrelu(g_asrc2[s] + adst));
    }
    float w = __expf(aself - m);
    float denom = w;
    float4 acc = make_float4(0.f, 0.f, 0.f, 0.f);
    if (lane < 10) {
        float4 hv = *(const float4*)&g_h2[node * 40 + lane * 4];
        acc = make_float4(w * hv.x, w * hv.y, w * hv.z, w * hv.w);
    }
    for (int e = beg; e < end; e++) {
        int s = g_csr[e];
        float wv = __expf(lrelu(g_asrc2[s] + adst) - m);
        denom += wv;
        if (lane < 10) {
            float4 v = *(const float4*)&g_h2[s * 40 + lane * 4];
            acc.x = fmaf(wv, v.x, acc.x);
            acc.y = fmaf(wv, v.y, acc.y);
            acc.z = fmaf(wv, v.z, acc.z);
            acc.w = fmaf(wv, v.w, acc.w);
        }
    }
    float inv = 1.f / (denom + 1e-16f);
    if (lane < 10) {
        float4 b = *(const float4*)&bias[lane * 4];
        *(float4*)&out[node * 40 + lane * 4] =
            make_float4(fmaf(acc.x, inv, b.x), fmaf(acc.y, inv, b.y),
                        fmaf(acc.z, inv, b.z), fmaf(acc.w, inv, b.w));
    }
}

// ---------------- launch ----------------------------------------------------
extern "C" void kernel_launch(void* const* d_in, const int* in_sizes, int n_in,
                              void* d_out, int out_size) {
    const float* x        = (const float*)d_in[0];
    const int*   ei       = (const int*)d_in[1];   // int32 (JAX x64 disabled)
    const float* W1       = (const float*)d_in[2];
    const float* att_src1 = (const float*)d_in[3];
    const float* att_dst1 = (const float*)d_in[4];
    const float* bias1    = (const float*)d_in[5];
    const float* W2       = (const float*)d_in[6];
    const float* att_src2 = (const float*)d_in[7];
    const float* att_dst2 = (const float*)d_in[8];
    const float* bias2    = (const float*)d_in[9];
    float* out = (float*)d_out;

    int N = in_sizes[0] / 128;
    int E = in_sizes[1] / 2;
    const int* src = ei;
    const int* dst = ei + E;

    float *h1p, *out1p, *h2p;
    int *cntp, *offp, *curp;
    cudaGetSymbolAddress((void**)&h1p, g_h1);
    cudaGetSymbolAddress((void**)&out1p, g_out1);
    cudaGetSymbolAddress((void**)&h2p, g_h2);
    cudaGetSymbolAddress((void**)&cntp, g_cnt);
    cudaGetSymbolAddress((void**)&offp, g_off);
    cudaGetSymbolAddress((void**)&curp, g_cursor);

    int smem1 = (128 * 136 + 64 * 132 + 256) * 4;   // 104448 B
    int smem2 = (128 * 40 + 32 * 132) * 4;          // 37376 B
    static bool attr_set = false;
    if (!attr_set) {
        cudaFuncSetAttribute(gemm1_tf32_kernel,
                             cudaFuncAttributeMaxDynamicSharedMemorySize, smem1);
        attr_set = true;
    }

    int eb = (E + 255) / 256;
    int wb = (N + 7) / 8;              // warp-per-node, 8 warps/block
    int gb1 = (N + 63) / 64;
    int gb2 = (N + 31) / 32;

    // CSR build (shared by both layers)
    cudaMemsetAsync(cntp, 0, (size_t)N * sizeof(int));
    hist_kernel<<<eb, 256>>>(dst, E);
    scan_kernel<<<1, 1024>>>(N);
    cudaMemcpyAsync(curp, offp, (size_t)N * sizeof(int), cudaMemcpyDeviceToDevice);
    scatter_kernel<<<eb, 256>>>(src, dst, E);

    // layer 1
    gemm1_tf32_kernel<<<gb1, 256, smem1>>>(x, W1, att_src1, att_dst1, h1p, N);
    agg1_kernel<<<wb, 256>>>(bias1, N);

    // layer 2
    gemm_kernel<40><<<gb2, 10 * 8, smem2>>>(out1p, W2, h2p, N);
    att2_kernel<<<wb, 256>>>(att_src2, att_dst2, N);
    agg2_kernel<<<wb, 256>>>(bias2, out, N);
}